// round 16
// baseline (speedup 1.0000x reference)
#include <cuda_runtime.h>
#include <cstddef>

// out[b,i,j]: pairwise-sorted, per-column cyclically shifted v (B=8, L=4096, D=1024 fp32).
//   s_j = (j==0) ? 0 : 2*(j-1)   (always even)
//   out pair (i, i+1), i even:  sort( v[(i-s_j)%L, j], v[(i+1-s_j)%L, j] )
//
// Tile: R=256 output rows x C=32 cols per CTA.  Grid: column-strip fastest
// (blockIdx.x = strip) so co-resident CTAs collectively read full DRAM rows.
// Smem band is PRE-SHIFTED per column with a 64-row margin on both sides:
//   store row for column j at band row rr is  rr - off_j + PAD  in [2, 383]
//   -> no predication in the load loop (5x LDG.128 + 20x STS.32, batched).
// Load  STS bank = rr+12q+3k -> 32 distinct -> conflict-free.
// Consume: 5x LDS.64 all at even float offsets (row-b read via even offset
//   base+STRIDE-1, stray lanes discarded), bank-pair (p+2q) mod 16 ->
//   conflict-free; then min/max + 2x streaming STG.128.

namespace {
constexpr int L      = 4096;
constexpr int D      = 1024;
constexpr int C      = 32;     // columns per tile
constexpr int R      = 256;    // output rows per tile
constexpr int STRIDE = 33;     // smem row stride (floats)
constexpr int PAD    = 64;     // margin rows
constexpr int ROWS   = R + 2 * PAD;   // 384
constexpr int BAND   = R + 64; // global rows loaded per tile
constexpr int NT     = 512;
constexpr size_t SMEM_BYTES = (size_t)ROWS * STRIDE * sizeof(float);  // 50688
}

__global__ __launch_bounds__(NT, 4)
void swd_kernel(const float* __restrict__ v, float* __restrict__ out) {
    extern __shared__ float s[];

    const int j0 = blockIdx.x * C;    // column strip (fastest)
    const int i0 = blockIdx.y * R;    // output row tile base (even)
    const int b  = blockIdx.z;

    const int q  = threadIdx.x & 7;   // column quad (4 cols)
    const int tr = threadIdx.x >> 3;  // 0..63

    const int j_hi      = j0 + C - 1;           // >= 31
    const int shift_hi  = 2 * (j_hi - 1);
    const int band_base = i0 - shift_hi;        // may be negative (mask wraps)

    const float* __restrict__ vb = v   + (size_t)b * (L * D);
    float*       __restrict__ ob = out + (size_t)b * (L * D);

    const int cb = 4 * q;

    // Per-column smem float offset: (PAD - off_k)*STRIDE + cb + k, off in [0,62]
    int sofs[4];
    #pragma unroll
    for (int k = 0; k < 4; k++) {
        int j   = j0 + cb + k;
        int sj  = (j == 0) ? 0 : 2 * (j - 1);
        sofs[k] = (PAD - (shift_hi - sj)) * STRIDE + cb + k;
    }

    // ---- Load band: 5x LDG.128 (batched, high MLP) + 20x unpredicated STS ----
    float4 val[BAND / 64];
    #pragma unroll
    for (int it = 0; it < BAND / 64; it++) {   // 5 independent loads
        int rr = it * 64 + tr;                 // band row 0..319
        int g  = (band_base + rr) & (L - 1);
        val[it] = *reinterpret_cast<const float4*>(vb + (size_t)g * D + (j0 + cb));
    }
    #pragma unroll
    for (int it = 0; it < BAND / 64; it++) {
        float* srow = s + (it * 64 + tr) * STRIDE;
        srow[sofs[0]] = val[it].x;
        srow[sofs[1]] = val[it].y;
        srow[sofs[2]] = val[it].z;
        srow[sofs[3]] = val[it].w;
    }
    __syncthreads();

    // ---- Consume: 5x LDS.64 + min/max + 2x STG.128 ----
    #pragma unroll
    for (int it = 0; it < (R / 2) * 8 / NT; it++) {   // 2 iterations
        int p = it * 64 + tr;                          // pair 0..127
        const float* base = s + (PAD + 2 * p) * STRIDE + cb;   // even offset
        float2 a01 = *reinterpret_cast<const float2*>(base);
        float2 a23 = *reinterpret_cast<const float2*>(base + 2);
        // Row b starts at base + STRIDE (odd). Read from even offset
        // base + STRIDE - 1; stray extracted lanes are in-bounds junk.
        const float* r1m = base + (STRIDE - 1);
        float2 t0 = *reinterpret_cast<const float2*>(r1m);       // {junk, b0}
        float2 t1 = *reinterpret_cast<const float2*>(r1m + 2);   // {b1, b2}
        float2 t2 = *reinterpret_cast<const float2*>(r1m + 4);   // {b3, junk}
        float b0 = t0.y, b1 = t1.x, b2 = t1.y, b3 = t2.x;
        float4 lo, hi;
        lo.x = fminf(a01.x, b0); hi.x = fmaxf(a01.x, b0);
        lo.y = fminf(a01.y, b1); hi.y = fmaxf(a01.y, b1);
        lo.z = fminf(a23.x, b2); hi.z = fmaxf(a23.x, b2);
        lo.w = fminf(a23.y, b3); hi.w = fmaxf(a23.y, b3);
        float* dst = ob + (size_t)(i0 + 2 * p) * D + (j0 + cb);
        __stcs(reinterpret_cast<float4*>(dst),     lo);
        __stcs(reinterpret_cast<float4*>(dst + D), hi);
    }
}

extern "C" void kernel_launch(void* const* d_in, const int* in_sizes, int n_in,
                              void* d_out, int out_size) {
    const float* v   = (const float*)d_in[0];
    float*       out = (float*)d_out;
    const int B = in_sizes[0] / (L * D);

    cudaFuncSetAttribute(swd_kernel,
                         cudaFuncAttributeMaxDynamicSharedMemorySize,
                         (int)SMEM_BYTES);

    dim3 grid(D / C, L / R, B);   // 32 x 16 x B, column-strip fastest
    swd_kernel<<<grid, NT, SMEM_BYTES>>>(v, out);
}

// round 17
// speedup vs baseline: 1.1332x; 1.1332x over previous
#include <cuda_runtime.h>
#include <cstddef>

// out[b,i,j]: pairwise-sorted, per-column cyclically shifted v (B=8, L=4096, D=1024 fp32).
//   s_j = (j==0) ? 0 : 2*(j-1)   (always even)
//   out pair (i, i+1), i even:  sort( v[(i-s_j)%L, j], v[(i+1-s_j)%L, j] )
//
// R5-bench structure (the measured best): tile R=256 rows x C=32 cols per CTA,
// column-strip-fastest grid; smem band PRE-SHIFTED per column, loads
// interleaved (LDG.128 immediately followed by its 4 predicated STS.32) to
// keep per-warp L1tex queue occupancy low — explicit batching measured slower.
// Consume: 8 scalar LDS (uniform 2-way bank pairs, cheaper than any
// vectorized alternative tried) + min/max + 2x streaming STG.128.
// This round: ALU diet only — single unsigned range check per store and
// hoisted per-column store base offsets.

namespace {
constexpr int L      = 4096;
constexpr int D      = 1024;
constexpr int C      = 32;    // columns per tile
constexpr int R      = 256;   // output rows per tile (even)
constexpr int STRIDE = 33;    // padded smem row stride in floats
constexpr int BAND   = R + 64;
constexpr int NT     = 512;
}

__global__ __launch_bounds__(NT)
void swd_kernel(const float* __restrict__ v, float* __restrict__ out) {
    __shared__ float s[R * STRIDE];   // 33792 bytes (static, as in best run)

    const int j0 = blockIdx.x * C;    // column strip (fastest)
    const int i0 = blockIdx.y * R;    // output row tile base (even)
    const int b  = blockIdx.z;

    const int q  = threadIdx.x & 7;   // column quad (4 cols)
    const int tr = threadIdx.x >> 3;  // 0..63

    const int j_hi      = j0 + C - 1;          // >= 31
    const int shift_hi  = 2 * (j_hi - 1);
    const int band_base = i0 - shift_hi;       // may be negative (mask wraps)

    const float* __restrict__ vb = v   + (size_t)b * (L * D);
    float*       __restrict__ ob = out + (size_t)b * (L * D);

    const int cb = 4 * q;

    // Hoisted per-column constants:
    //   off_k  = shift_hi - s_{j0+cb+k}  in [0, 62]
    //   sbase_k = cb + k - off_k*STRIDE  (store float-offset sans rr term)
    int off_[4], sbase[4];
    #pragma unroll
    for (int k = 0; k < 4; k++) {
        int j   = j0 + cb + k;
        int sj  = (j == 0) ? 0 : 2 * (j - 1);
        off_[k] = shift_hi - sj;
        sbase[k] = cb + k - off_[k] * STRIDE;
    }

    // ---- Load band: interleaved LDG.128 + 4 predicated STS.32 ----
    #pragma unroll
    for (int it = 0; it < BAND / 64; it++) {      // 5 iterations
        int rr = it * 64 + tr;                    // band row 0..319
        int g  = (band_base + rr) & (L - 1);
        float4 val = *reinterpret_cast<const float4*>(vb + (size_t)g * D + (j0 + cb));
        float vv[4] = {val.x, val.y, val.z, val.w};
        int rbase = rr * STRIDE;
        #pragma unroll
        for (int k = 0; k < 4; k++) {
            if ((unsigned)(rr - off_[k]) < (unsigned)R)   // single ISETP
                s[rbase + sbase[k]] = vv[k];
        }
    }
    __syncthreads();

    // ---- Consume: 8 scalar LDS + min/max + 2x STG.128 streaming ----
    #pragma unroll
    for (int it = 0; it < (R / 2) * 8 / NT; it++) {   // 2 iterations
        int p = it * 64 + tr;                          // pair 0..127
        const float* r0 = s + (2 * p) * STRIDE + cb;
        const float* r1 = r0 + STRIDE;
        float a0 = r0[0], a1 = r0[1], a2 = r0[2], a3 = r0[3];
        float b0 = r1[0], b1 = r1[1], b2 = r1[2], b3 = r1[3];
        float4 lo, hi;
        lo.x = fminf(a0, b0); hi.x = fmaxf(a0, b0);
        lo.y = fminf(a1, b1); hi.y = fmaxf(a1, b1);
        lo.z = fminf(a2, b2); hi.z = fmaxf(a2, b2);
        lo.w = fminf(a3, b3); hi.w = fmaxf(a3, b3);
        float* dst = ob + (size_t)(i0 + 2 * p) * D + (j0 + cb);
        __stcs(reinterpret_cast<float4*>(dst),     lo);
        __stcs(reinterpret_cast<float4*>(dst + D), hi);
    }
}

extern "C" void kernel_launch(void* const* d_in, const int* in_sizes, int n_in,
                              void* d_out, int out_size) {
    const float* v   = (const float*)d_in[0];
    float*       out = (float*)d_out;
    const int B = in_sizes[0] / (L * D);

    dim3 grid(D / C, L / R, B);   // 32 x 16 x B, column-strip fastest
    swd_kernel<<<grid, NT>>>(v, out);
}